// round 15
// baseline (speedup 1.0000x reference)
#include <cuda_runtime.h>
#include <cstdint>

// Problem constants
#define NP 21504   // priors per image
#define HALF 10752 // NP/2
#define KC 1024    // top-k
#define BB 64      // batch
#define NT 512     // threads per block (kSB)
#define NTA 1024   // threads per block (kHA)
#define WORDS 32   // KC/32 mask words
#define CCAP 4096  // candidate buffer
#define SLICES 8   // supmat blocks per image
#define WPS 4      // words per slice
#define NBIN 8192  // 13-bit monotone-d histogram

// ---------------- global scratch (device globals: no allocs) ----------------
__device__ unsigned int       g_hist[BB * 2 * NBIN];   // 4 MB
__device__ unsigned long long g_keys[BB * KC];
__device__ float4             g_box[BB * KC];          // x1,y1,x2,y2
__device__ float              g_bar[BB * KC];
__device__ unsigned int       g_sup[BB * WORDS * KC];  // w-major, upper tri only
__device__ unsigned int       g_rowany[BB * SLICES * 32];
__device__ int                g_cnt1[BB];              // kHA election (0-init)
__device__ int                g_cnt2[BB];              // kSB election (0-init)

// monotone map: float bits -> unsigned preserving float ordering
__device__ __forceinline__ unsigned int fmap(float f) {
    unsigned int b = __float_as_uint(f);
    return ((int)b < 0) ? ~b : (b | 0x80000000u);
}

// ===================== kHA: hist (all) + select/sort/decode (elected) ========
// SMEM layout (bytes)
#define KA_KEYS   0        // 32768: u64[4096]
#define KA_HIST   32768    // 32768: u32[8192]
#define KA_WSUM   65536    // 128
#define KA_MISC   65664    // 32
#define KA_TOTAL  65696

__global__ __launch_bounds__(NTA, 1)
void kHA(const float* __restrict__ locs,
         const float* __restrict__ confs,
         const float* __restrict__ priors)
{
    extern __shared__ unsigned char sm[];
    unsigned long long* s_keys = (unsigned long long*)(sm + KA_KEYS);
    unsigned int*       s_hist = (unsigned int*)(sm + KA_HIST);
    unsigned int*       s_wsum = (unsigned int*)(sm + KA_WSUM);
    int*                s_misc = (int*)(sm + KA_MISC);

    const int b    = blockIdx.y;
    const int half = blockIdx.x;
    const int tid  = threadIdx.x;
    const int lane = tid & 31;
    const int wid  = tid >> 5;
    const unsigned FULL = 0xffffffffu;

    // ---- Phase A (all blocks): own-half histogram ----
    for (int i = tid; i < NBIN; i += NTA) s_hist[i] = 0;
    __syncthreads();
    const float* conf = confs + (size_t)b * NP * 2;
    const int n0 = half * HALF;
    for (int n = n0 + tid; n < n0 + HALF; n += NTA) {
        float2 c = __ldg((const float2*)(conf + 2 * n));
        float d = __fsub_rn(c.y, c.x);
        atomicAdd(&s_hist[fmap(d) >> 19], 1u);
    }
    __syncthreads();
    for (int i = tid; i < NBIN; i += NTA)
        g_hist[((b * 2 + half) << 13) + i] = s_hist[i];

    // ---- election: last block of this image proceeds ----
    __threadfence();
    __syncthreads();
    if (tid == 0) s_misc[2] = atomicAdd(&g_cnt1[b], 1);
    __syncthreads();
    if (s_misc[2] != 1) return;          // first arriver exits
    if (tid == 0) g_cnt1[b] = 0;         // reset for graph replay
    __threadfence();                      // acquire other half's hist
    __syncthreads();

    // ---- add other half's histogram ----
    for (int i = tid; i < NBIN; i += NTA)
        s_hist[i] += g_hist[((b * 2 + (1 - half)) << 13) + i];
    if (tid == 0) s_misc[0] = 0;
    __syncthreads();

    // ---- suffix scan over 8192 bins (8 bins/thread, 32 warps) ----
    {
        unsigned int v[8], S = 0;
        #pragma unroll
        for (int k = 0; k < 8; k++) { v[k] = s_hist[8 * tid + k]; S += v[k]; }
        unsigned int sfx = S;
        #pragma unroll
        for (int off = 1; off < 32; off <<= 1) {
            unsigned int u = __shfl_down_sync(FULL, sfx, off);
            if (lane + off < 32) sfx += u;
        }
        if (lane == 0) s_wsum[wid] = sfx;   // warp total
        __syncthreads();
        unsigned int cross = 0;
        for (int w2 = wid + 1; w2 < 32; w2++) cross += s_wsum[w2];
        unsigned int T_t = sfx + cross;     // suffix over threads >= tid
        unsigned int sb[9];
        sb[8] = T_t - S;
        #pragma unroll
        for (int k = 7; k >= 0; k--) sb[k] = sb[k + 1] + v[k];
        #pragma unroll
        for (int k = 0; k < 8; k++)
            if (sb[k] >= (unsigned)KC && sb[k + 1] < (unsigned)KC)
                s_misc[1] = 8 * tid + k;    // binK (exactly one writer)
    }
    for (int i = tid; i < CCAP; i += NTA) s_keys[i] = 0ULL;
    __syncthreads();

    // collect cutoff: one bin below binK (margin swallows any s-tie plateau)
    int binC = s_misc[1] - 1; if (binC < 0) binC = 0;
    const unsigned int Tu = (unsigned int)binC << 19;

    // ---- collect candidates (recompute d from confs); exact s for them ----
    for (int n = tid; n < NP; n += NTA) {
        float2 c = __ldg((const float2*)(conf + 2 * n));
        float d = __fsub_rn(c.y, c.x);
        bool cc = (fmap(d) >= Tu);
        unsigned int bal = __ballot_sync(FULL, cc);
        if (bal) {
            int leader = __ffs(bal) - 1;
            int base = 0;
            if (lane == leader) base = atomicAdd(&s_misc[0], __popc(bal));
            base = __shfl_sync(FULL, base, leader);
            if (cc) {
                int p = base + __popc(bal & ((1u << lane) - 1u));
                if (p < CCAP) {
                    // exact reference softmax from rounded d (bit-identical)
                    float s;
                    if (d >= 0.0f) {
                        float e0 = expf(-d);           // = expf(fsub(cx,cy))
                        s = __fdiv_rn(1.0f, __fadd_rn(e0, 1.0f));
                    } else {
                        float e1 = expf(d);
                        s = __fdiv_rn(e1, __fadd_rn(1.0f, e1));
                    }
                    s_keys[p] = ((unsigned long long)__float_as_uint(s) << 32) |
                                (unsigned int)(~n);
                }
            }
        }
    }
    __syncthreads();

    // ---- bitonic sort descending (hybrid warp/SMEM network) ----
    if (s_misc[0] <= 2048) {
        const int e0 = (wid << 6) + lane;
        const int e1 = e0 + 32;
        unsigned long long a = s_keys[e0], b2 = s_keys[e1];

        #pragma unroll
        for (int k = 2; k <= 64; k <<= 1) {
            if (k == 64) {
                bool desc = ((e0 & 64) == 0);
                if (desc ? (a < b2) : (a > b2)) {
                    unsigned long long t2 = a; a = b2; b2 = t2;
                }
            }
            #pragma unroll
            for (int j = (k == 64 ? 16 : (k >> 1)); j > 0; j >>= 1) {
                unsigned long long pa = __shfl_xor_sync(FULL, a, j);
                unsigned long long pb = __shfl_xor_sync(FULL, b2, j);
                bool km0 = (((e0 & j) == 0) == ((e0 & k) == 0));
                bool km1 = (((e1 & j) == 0) == ((e1 & k) == 0));
                a  = km0 ? (a  > pa ? a  : pa) : (a  < pa ? a  : pa);
                b2 = km1 ? (b2 > pb ? b2 : pb) : (b2 < pb ? b2 : pb);
            }
        }
        s_keys[e0] = a; s_keys[e1] = b2;
        __syncthreads();

        for (int k = 128; k <= 2048; k <<= 1) {
            for (int j = k >> 1; j >= 64; j >>= 1) {
                #pragma unroll
                for (int rep = 0; rep < 2; rep++) {
                    int i = tid + rep * NTA;
                    int ixj = i ^ j;
                    if (ixj > i) {
                        unsigned long long x = s_keys[i];
                        unsigned long long y = s_keys[ixj];
                        bool desc = ((i & k) == 0);
                        if (desc ? (x < y) : (x > y)) {
                            s_keys[i] = y; s_keys[ixj] = x;
                        }
                    }
                }
                __syncthreads();
            }
            a = s_keys[e0]; b2 = s_keys[e1];
            {
                bool desc = ((e0 & k) == 0);
                if (desc ? (a < b2) : (a > b2)) {
                    unsigned long long t2 = a; a = b2; b2 = t2;
                }
            }
            #pragma unroll
            for (int j = 16; j > 0; j >>= 1) {
                unsigned long long pa = __shfl_xor_sync(FULL, a, j);
                unsigned long long pb = __shfl_xor_sync(FULL, b2, j);
                bool km0 = (((e0 & j) == 0) == ((e0 & k) == 0));
                bool km1 = (((e1 & j) == 0) == ((e1 & k) == 0));
                a  = km0 ? (a  > pa ? a  : pa) : (a  < pa ? a  : pa);
                b2 = km1 ? (b2 > pb ? b2 : pb) : (b2 < pb ? b2 : pb);
            }
            s_keys[e0] = a; s_keys[e1] = b2;
            __syncthreads();
        }
    } else {
        for (int k = 2; k <= CCAP; k <<= 1) {
            for (int j = k >> 1; j > 0; j >>= 1) {
                for (int i = tid; i < CCAP; i += NTA) {
                    int ixj = i ^ j;
                    if (ixj > i) {
                        unsigned long long x = s_keys[i];
                        unsigned long long y = s_keys[ixj];
                        bool desc = ((i & k) == 0);
                        if (desc ? (x < y) : (x > y)) {
                            s_keys[i] = y; s_keys[ixj] = x;
                        }
                    }
                }
                __syncthreads();
            }
        }
    }

    // ---- decode boxes (no FMA contraction) + write scratch ----
    const float* loc = locs + (size_t)b * NP * 4;
    for (int t = tid; t < KC; t += NTA) {
        unsigned long long key = s_keys[t];
        int idx = (int)(~(unsigned int)key);
        float4 l = __ldg((const float4*)(loc + 4 * (size_t)idx));
        float4 p = __ldg((const float4*)(priors + 4 * (size_t)idx));
        float cx = __fadd_rn(p.x, __fmul_rn(__fmul_rn(l.x, 0.1f), p.z));
        float cy = __fadd_rn(p.y, __fmul_rn(__fmul_rn(l.y, 0.1f), p.w));
        float w  = __fmul_rn(p.z, expf(__fmul_rn(l.z, 0.2f)));
        float h  = __fmul_rn(p.w, expf(__fmul_rn(l.w, 0.2f)));
        float x1 = __fsub_rn(cx, __fdiv_rn(w, 2.0f));
        float y1 = __fsub_rn(cy, __fdiv_rn(h, 2.0f));
        float x2 = __fadd_rn(x1, w);
        float y2 = __fadd_rn(y1, h);
        size_t o = (size_t)b * KC + t;
        g_box[o] = make_float4(x1, y1, x2, y2);
        float aw = fmaxf(__fsub_rn(x2, x1), 0.0f);
        float ah = fmaxf(__fsub_rn(y2, y1), 0.0f);
        g_bar[o] = __fmul_rn(aw, ah);
        g_keys[o] = key;
    }
}

// ===================== kSB: supmat (all) + NMS scan/output (elected) =========
// iou > 0.4  <=>  3.5*inter > ai+aj  (reals). Band constants give +-5.7e-5
// relative margin >> rounding skew; in-band -> exact reference computation.
#define C_SUP  3.4998f
#define C_NOT  3.5002f

__device__ __forceinline__ bool iou_sup(float4 bi, float ai,
                                        float4 bj, float aj)
{
    float lx = fmaxf(bi.x, bj.x);
    float ly = fmaxf(bi.y, bj.y);
    float rx = fminf(bi.z, bj.z);
    float ry = fminf(bi.w, bj.w);
    float ww = fmaxf(__fsub_rn(rx, lx), 0.0f);
    float hh = fmaxf(__fsub_rn(ry, ly), 0.0f);
    float inter = __fmul_rn(ww, hh);
    float P = __fadd_rn(ai, aj);
    bool sup  = __fmaf_rn(C_SUP, inter, -P) > 0.0f;   // definitely > 0.4
    bool nsup = __fmaf_rn(C_NOT, inter, -P) < 0.0f;   // definitely <= 0.4
    if (!sup && !nsup) {   // rare band: exact reference
        float um = __fsub_rn(P, inter);
        sup = (__fdiv_rn(inter, fmaxf(um, 1e-9f)) > 0.4f);
    }
    return sup;
}

__global__ __launch_bounds__(NT)
void kSB(float* __restrict__ out, int out_size)
{
    __shared__ float4 s_box[KC];
    __shared__ float  s_area[KC];
    __shared__ float  s_sc[KC];
    __shared__ unsigned char s_rowf[KC];
    __shared__ unsigned int  s_diag[KC];
    __shared__ unsigned int  s_raw[32], s_validw[32], s_keepw[32], s_diagm[32];
    __shared__ int s_flag;

    const int b     = blockIdx.y;
    const int slice = blockIdx.x;
    const int tid   = threadIdx.x;
    const int lane  = tid & 31;
    const unsigned FULL = 0xffffffffu;

    // ---- load boxes/areas/scores ----
    for (int t = tid; t < KC; t += NT) {
        size_t o = (size_t)b * KC + t;
        s_box[t] = g_box[o];
        s_area[t] = g_bar[o];
        s_sc[t] = __uint_as_float((unsigned int)(g_keys[o] >> 32));
        s_rowf[t] = 0;
    }
    __syncthreads();

    // ---- supmat slice (stride-8 word interleave) ----
    unsigned int* supb = g_sup + (size_t)b * WORDS * KC;
    for (int t = tid; t < WPS * KC; t += NT) {
        int w  = slice + ((t >> 10) << 3);  // stride-8 interleave: balanced
        int i  = t & 1023;                  // consecutive across lanes
        int j0 = w << 5;
        int ibase = i & ~31;                // warp-uniform
        unsigned int m = 0;
        float4 bi = s_box[i];
        float  ai = s_area[i];
        if (j0 >= ibase + 32) {
            #pragma unroll 4
            for (int jj = 0; jj < 32; jj++) {
                int j = j0 + jj;            // warp-uniform -> broadcast LDS
                if (iou_sup(bi, ai, s_box[j], s_area[j])) m |= (1u << jj);
            }
        } else if (j0 + 31 > i) {
            #pragma unroll 4
            for (int jj = 0; jj < 32; jj++) {
                int j = j0 + jj;
                if (j <= i) continue;
                if (iou_sup(bi, ai, s_box[j], s_area[j])) m |= (1u << jj);
            }
        }
        if (w >= (i >> 5)) supb[(w << 10) + i] = m;   // upper tri only
        if (m) s_rowf[i] = 1;               // benign race (writes of 1)
    }
    __syncthreads();
    for (int r = tid; r < KC; r += NT) {
        unsigned int bal = __ballot_sync(FULL, s_rowf[r] != 0);
        if (lane == 0)
            g_rowany[((b * SLICES + slice) << 5) + (r >> 5)] = bal;
    }

    // ---- election: last-arriving slice block does the scan ----
    __threadfence();
    __syncthreads();
    if (tid == 0) s_flag = atomicAdd(&g_cnt2[b], 1);
    __syncthreads();
    if (s_flag != SLICES - 1) return;
    if (tid == 0) g_cnt2[b] = 0;          // reset for graph replay
    __threadfence();                       // acquire peers' g_sup/g_rowany
    __syncthreads();

    // ---- validity + rowany ----
    for (int t = tid; t < KC; t += NT) {
        unsigned int bal = __ballot_sync(FULL, s_sc[t] > 0.5f);
        if (lane == 0) s_validw[t >> 5] = bal;
    }
    if (tid < 32) {
        unsigned int ra = 0;
        #pragma unroll
        for (int sl = 0; sl < SLICES; sl++)
            ra |= g_rowany[((b * SLICES + sl) << 5) + tid];
        s_raw[tid] = ra;
    }
    __syncthreads();

    // ---- stage diagonal words (4 KB, coalesced) + diag mask ----
    for (int t = tid; t < KC; t += NT)
        s_diag[t] = supb[((t >> 5) << 10) + t];
    __syncthreads();
    for (int t = tid; t < KC; t += NT) {
        int w = t >> 5;   // warp-uniform
        unsigned int nd = (s_raw[w] & s_validw[w]) >> (t & 31);
        bool dg = (nd & 1u) && (s_diag[t] != 0u);
        unsigned int bal = __ballot_sync(FULL, dg);
        if (lane == 0) s_diagm[w] = bal;
    }
    __syncthreads();

    // ---- greedy scan: one warp; applies read rows straight from L2 ----
    if (tid < 32) {
        unsigned int remv = 0;   // lane holds removed-mask for column word lane
        for (int w = 0; w < 32; w++) {
            unsigned int rm_w = __shfl_sync(FULL, remv, w);
            unsigned int vw = s_validw[w];
            unsigned int ra = s_raw[w];
            unsigned int diag = s_diagm[w];
            unsigned int kw = 0;
            unsigned int remaining = vw & ra;
            for (;;) {
                unsigned int scand = remaining & ~rm_w;
                if (!scand) break;
                unsigned int dcand = scand & diag;
                if (!dcand) { kw |= scand; break; }
                int d = __ffs(dcand) - 1;
                unsigned int below = scand & ((1u << d) - 1u);
                kw |= below | (1u << d);
                remaining &= ~(below | (1u << d));
                rm_w |= s_diag[(w << 5) + d];   // diag word from SMEM
            }
            kw |= vw & ~ra & ~rm_w;
            if (lane == 0) s_keepw[w] = kw;
            // batch apply: kept suppressors -> columns >= w (upper tri, L2)
            unsigned int app = kw & ra;
            while (app) {
                int bit = __ffs(app) - 1;
                app &= app - 1u;
                if (lane >= w)
                    remv |= supb[((unsigned)lane << 10) + (w << 5) + bit];
            }
        }
    }
    __syncthreads();

    // ---- outputs: dets [B,KC,5], keep [B,KC] ----
    const bool write_keep = (out_size >= BB * KC * 6);
    for (int t = tid; t < KC; t += NT) {
        bool kept = (s_keepw[t >> 5] >> (t & 31)) & 1u;
        float kf = kept ? 1.0f : 0.0f;
        float4 bx = s_box[t];
        size_t base = ((size_t)b * KC + t) * 5;
        out[base + 0] = __fmul_rn(bx.x, kf);
        out[base + 1] = __fmul_rn(bx.y, kf);
        out[base + 2] = __fmul_rn(bx.z, kf);
        out[base + 3] = __fmul_rn(bx.w, kf);
        out[base + 4] = __fmul_rn(s_sc[t], kf);
        if (write_keep)
            out[(size_t)BB * KC * 5 + (size_t)b * KC + t] = kf;
    }
}

// ======================= launch ==============================================
extern "C" void kernel_launch(void* const* d_in, const int* in_sizes, int n_in,
                              void* d_out, int out_size)
{
    (void)in_sizes; (void)n_in;
    cudaFuncSetAttribute(kHA,
        cudaFuncAttributeMaxDynamicSharedMemorySize, KA_TOTAL);
    const float* locs   = (const float*)d_in[0];
    const float* confs  = (const float*)d_in[1];
    const float* priors = (const float*)d_in[2];
    float* out = (float*)d_out;

    kHA<<<dim3(2, BB), NTA, KA_TOTAL>>>(locs, confs, priors);
    kSB<<<dim3(SLICES, BB), NT>>>(out, out_size);
}

// round 16
// speedup vs baseline: 1.0709x; 1.0709x over previous
#include <cuda_runtime.h>
#include <cstdint>

// Problem constants
#define NP 21504   // priors per image
#define HALF 10752 // NP/2
#define KC 1024    // top-k
#define BB 64      // batch
#define NT 512     // threads per block (kS, kB)
#define NTA 1024   // threads per block (kHA)
#define WORDS 32   // KC/32 mask words
#define CCAP 4096  // candidate buffer
#define SLICES 8   // supmat blocks per image
#define WPS 4      // words per slice
#define NBIN 8192  // 13-bit monotone-d histogram
#define PLANE 1028 // kB SMEM plane stride (words): 16B-aligned, 4-way max conflict

// ---------------- global scratch (device globals: no allocs) ----------------
__device__ unsigned int       g_hist[BB * 2 * NBIN];   // 4 MB
__device__ unsigned long long g_keys[BB * KC];
__device__ float4             g_box[BB * KC];          // x1,y1,x2,y2
__device__ float              g_bar[BB * KC];
__device__ unsigned int       g_sup[BB * WORDS * KC];  // w-major, upper tri only
__device__ unsigned int       g_rowany[BB * SLICES * 32];
__device__ int                g_cnt1[BB];              // kHA election (0-init)

// monotone map: float bits -> unsigned preserving float ordering
__device__ __forceinline__ unsigned int fmap(float f) {
    unsigned int b = __float_as_uint(f);
    return ((int)b < 0) ? ~b : (b | 0x80000000u);
}

// ===================== kHA: hist (all) + select/sort/decode (elected) ========
// SMEM layout (bytes)
#define KA_KEYS   0        // 32768: u64[4096]
#define KA_HIST   32768    // 32768: u32[8192]
#define KA_WSUM   65536    // 128
#define KA_MISC   65664    // 32
#define KA_TOTAL  65696

__global__ __launch_bounds__(NTA, 1)
void kHA(const float* __restrict__ locs,
         const float* __restrict__ confs,
         const float* __restrict__ priors)
{
    extern __shared__ unsigned char sm[];
    unsigned long long* s_keys = (unsigned long long*)(sm + KA_KEYS);
    unsigned int*       s_hist = (unsigned int*)(sm + KA_HIST);
    unsigned int*       s_wsum = (unsigned int*)(sm + KA_WSUM);
    int*                s_misc = (int*)(sm + KA_MISC);

    const int b    = blockIdx.y;
    const int half = blockIdx.x;
    const int tid  = threadIdx.x;
    const int lane = tid & 31;
    const int wid  = tid >> 5;
    const unsigned FULL = 0xffffffffu;

    // ---- Phase A (all blocks): own-half histogram ----
    for (int i = tid; i < NBIN; i += NTA) s_hist[i] = 0;
    __syncthreads();
    const float* conf = confs + (size_t)b * NP * 2;
    const int n0 = half * HALF;
    for (int n = n0 + tid; n < n0 + HALF; n += NTA) {
        float2 c = __ldg((const float2*)(conf + 2 * n));
        float d = __fsub_rn(c.y, c.x);
        atomicAdd(&s_hist[fmap(d) >> 19], 1u);
    }
    __syncthreads();
    for (int i = tid; i < NBIN; i += NTA)
        g_hist[((b * 2 + half) << 13) + i] = s_hist[i];

    // ---- election: last block of this image proceeds ----
    __threadfence();
    __syncthreads();
    if (tid == 0) s_misc[2] = atomicAdd(&g_cnt1[b], 1);
    __syncthreads();
    if (s_misc[2] != 1) return;          // first arriver exits
    if (tid == 0) g_cnt1[b] = 0;         // reset for graph replay
    __threadfence();                      // acquire other half's hist
    __syncthreads();

    // ---- add other half's histogram ----
    for (int i = tid; i < NBIN; i += NTA)
        s_hist[i] += g_hist[((b * 2 + (1 - half)) << 13) + i];
    if (tid == 0) s_misc[0] = 0;
    __syncthreads();

    // ---- suffix scan over 8192 bins (8 bins/thread, 32 warps) ----
    {
        unsigned int v[8], S = 0;
        #pragma unroll
        for (int k = 0; k < 8; k++) { v[k] = s_hist[8 * tid + k]; S += v[k]; }
        unsigned int sfx = S;
        #pragma unroll
        for (int off = 1; off < 32; off <<= 1) {
            unsigned int u = __shfl_down_sync(FULL, sfx, off);
            if (lane + off < 32) sfx += u;
        }
        if (lane == 0) s_wsum[wid] = sfx;   // warp total
        __syncthreads();
        unsigned int cross = 0;
        for (int w2 = wid + 1; w2 < 32; w2++) cross += s_wsum[w2];
        unsigned int T_t = sfx + cross;     // suffix over threads >= tid
        unsigned int sb[9];
        sb[8] = T_t - S;
        #pragma unroll
        for (int k = 7; k >= 0; k--) sb[k] = sb[k + 1] + v[k];
        #pragma unroll
        for (int k = 0; k < 8; k++)
            if (sb[k] >= (unsigned)KC && sb[k + 1] < (unsigned)KC)
                s_misc[1] = 8 * tid + k;    // binK (exactly one writer)
    }
    for (int i = tid; i < CCAP; i += NTA) s_keys[i] = 0ULL;
    __syncthreads();

    // collect cutoff: one bin below binK (margin swallows any s-tie plateau)
    int binC = s_misc[1] - 1; if (binC < 0) binC = 0;
    const unsigned int Tu = (unsigned int)binC << 19;

    // ---- collect candidates (recompute d from confs); exact s for them ----
    for (int n = tid; n < NP; n += NTA) {
        float2 c = __ldg((const float2*)(conf + 2 * n));
        float d = __fsub_rn(c.y, c.x);
        bool cc = (fmap(d) >= Tu);
        unsigned int bal = __ballot_sync(FULL, cc);
        if (bal) {
            int leader = __ffs(bal) - 1;
            int base = 0;
            if (lane == leader) base = atomicAdd(&s_misc[0], __popc(bal));
            base = __shfl_sync(FULL, base, leader);
            if (cc) {
                int p = base + __popc(bal & ((1u << lane) - 1u));
                if (p < CCAP) {
                    // exact reference softmax from rounded d (bit-identical)
                    float s;
                    if (d >= 0.0f) {
                        float e0 = expf(-d);           // = expf(fsub(cx,cy))
                        s = __fdiv_rn(1.0f, __fadd_rn(e0, 1.0f));
                    } else {
                        float e1 = expf(d);
                        s = __fdiv_rn(e1, __fadd_rn(1.0f, e1));
                    }
                    s_keys[p] = ((unsigned long long)__float_as_uint(s) << 32) |
                                (unsigned int)(~n);
                }
            }
        }
    }
    __syncthreads();

    // ---- bitonic sort descending (hybrid warp/SMEM network) ----
    if (s_misc[0] <= 2048) {
        const int e0 = (wid << 6) + lane;
        const int e1 = e0 + 32;
        unsigned long long a = s_keys[e0], b2 = s_keys[e1];

        #pragma unroll
        for (int k = 2; k <= 64; k <<= 1) {
            if (k == 64) {
                bool desc = ((e0 & 64) == 0);
                if (desc ? (a < b2) : (a > b2)) {
                    unsigned long long t2 = a; a = b2; b2 = t2;
                }
            }
            #pragma unroll
            for (int j = (k == 64 ? 16 : (k >> 1)); j > 0; j >>= 1) {
                unsigned long long pa = __shfl_xor_sync(FULL, a, j);
                unsigned long long pb = __shfl_xor_sync(FULL, b2, j);
                bool km0 = (((e0 & j) == 0) == ((e0 & k) == 0));
                bool km1 = (((e1 & j) == 0) == ((e1 & k) == 0));
                a  = km0 ? (a  > pa ? a  : pa) : (a  < pa ? a  : pa);
                b2 = km1 ? (b2 > pb ? b2 : pb) : (b2 < pb ? b2 : pb);
            }
        }
        s_keys[e0] = a; s_keys[e1] = b2;
        __syncthreads();

        for (int k = 128; k <= 2048; k <<= 1) {
            for (int j = k >> 1; j >= 64; j >>= 1) {
                #pragma unroll
                for (int rep = 0; rep < 2; rep++) {
                    int i = tid + rep * NTA;
                    int ixj = i ^ j;
                    if (ixj > i) {
                        unsigned long long x = s_keys[i];
                        unsigned long long y = s_keys[ixj];
                        bool desc = ((i & k) == 0);
                        if (desc ? (x < y) : (x > y)) {
                            s_keys[i] = y; s_keys[ixj] = x;
                        }
                    }
                }
                __syncthreads();
            }
            a = s_keys[e0]; b2 = s_keys[e1];
            {
                bool desc = ((e0 & k) == 0);
                if (desc ? (a < b2) : (a > b2)) {
                    unsigned long long t2 = a; a = b2; b2 = t2;
                }
            }
            #pragma unroll
            for (int j = 16; j > 0; j >>= 1) {
                unsigned long long pa = __shfl_xor_sync(FULL, a, j);
                unsigned long long pb = __shfl_xor_sync(FULL, b2, j);
                bool km0 = (((e0 & j) == 0) == ((e0 & k) == 0));
                bool km1 = (((e1 & j) == 0) == ((e1 & k) == 0));
                a  = km0 ? (a  > pa ? a  : pa) : (a  < pa ? a  : pa);
                b2 = km1 ? (b2 > pb ? b2 : pb) : (b2 < pb ? b2 : pb);
            }
            s_keys[e0] = a; s_keys[e1] = b2;
            __syncthreads();
        }
    } else {
        for (int k = 2; k <= CCAP; k <<= 1) {
            for (int j = k >> 1; j > 0; j >>= 1) {
                for (int i = tid; i < CCAP; i += NTA) {
                    int ixj = i ^ j;
                    if (ixj > i) {
                        unsigned long long x = s_keys[i];
                        unsigned long long y = s_keys[ixj];
                        bool desc = ((i & k) == 0);
                        if (desc ? (x < y) : (x > y)) {
                            s_keys[i] = y; s_keys[ixj] = x;
                        }
                    }
                }
                __syncthreads();
            }
        }
    }

    // ---- decode boxes (no FMA contraction) + write scratch ----
    const float* loc = locs + (size_t)b * NP * 4;
    for (int t = tid; t < KC; t += NTA) {
        unsigned long long key = s_keys[t];
        int idx = (int)(~(unsigned int)key);
        float4 l = __ldg((const float4*)(loc + 4 * (size_t)idx));
        float4 p = __ldg((const float4*)(priors + 4 * (size_t)idx));
        float cx = __fadd_rn(p.x, __fmul_rn(__fmul_rn(l.x, 0.1f), p.z));
        float cy = __fadd_rn(p.y, __fmul_rn(__fmul_rn(l.y, 0.1f), p.w));
        float w  = __fmul_rn(p.z, expf(__fmul_rn(l.z, 0.2f)));
        float h  = __fmul_rn(p.w, expf(__fmul_rn(l.w, 0.2f)));
        float x1 = __fsub_rn(cx, __fdiv_rn(w, 2.0f));
        float y1 = __fsub_rn(cy, __fdiv_rn(h, 2.0f));
        float x2 = __fadd_rn(x1, w);
        float y2 = __fadd_rn(y1, h);
        size_t o = (size_t)b * KC + t;
        g_box[o] = make_float4(x1, y1, x2, y2);
        float aw = fmaxf(__fsub_rn(x2, x1), 0.0f);
        float ah = fmaxf(__fsub_rn(y2, y1), 0.0f);
        g_bar[o] = __fmul_rn(aw, ah);
        g_keys[o] = key;
    }
}

// ===================== kS: suppression bitmatrix (8 slices, interleaved) =====
// iou > 0.4  <=>  3.5*inter > ai+aj  (reals). Band constants give +-5.7e-5
// relative margin >> rounding skew; in-band -> exact reference computation.
#define C_SUP  3.4998f
#define C_NOT  3.5002f

__device__ __forceinline__ bool iou_sup(float4 bi, float ai,
                                        float4 bj, float aj)
{
    float lx = fmaxf(bi.x, bj.x);
    float ly = fmaxf(bi.y, bj.y);
    float rx = fminf(bi.z, bj.z);
    float ry = fminf(bi.w, bj.w);
    float ww = fmaxf(__fsub_rn(rx, lx), 0.0f);
    float hh = fmaxf(__fsub_rn(ry, ly), 0.0f);
    float inter = __fmul_rn(ww, hh);
    float P = __fadd_rn(ai, aj);
    bool sup  = __fmaf_rn(C_SUP, inter, -P) > 0.0f;   // definitely > 0.4
    bool nsup = __fmaf_rn(C_NOT, inter, -P) < 0.0f;   // definitely <= 0.4
    if (!sup && !nsup) {   // rare band: exact reference
        float um = __fsub_rn(P, inter);
        sup = (__fdiv_rn(inter, fmaxf(um, 1e-9f)) > 0.4f);
    }
    return sup;
}

__global__ __launch_bounds__(NT)
void kS_supmat()
{
    __shared__ float4 s_box[KC];
    __shared__ float  s_area[KC];
    __shared__ unsigned char s_rowf[KC];

    const int b     = blockIdx.y;
    const int slice = blockIdx.x;
    const int tid   = threadIdx.x;
    const int lane  = tid & 31;

    for (int t = tid; t < KC; t += NT) {
        size_t o = (size_t)b * KC + t;
        s_box[t] = g_box[o];
        s_area[t] = g_bar[o];
        s_rowf[t] = 0;
    }
    __syncthreads();

    unsigned int* supb = g_sup + (size_t)b * WORDS * KC;
    for (int t = tid; t < WPS * KC; t += NT) {
        int w  = slice + ((t >> 10) << 3);  // stride-8 interleave: balanced
        int i  = t & 1023;                  // consecutive across lanes
        int j0 = w << 5;
        int ibase = i & ~31;                // warp-uniform
        unsigned int m = 0;
        float4 bi = s_box[i];
        float  ai = s_area[i];
        if (j0 >= ibase + 32) {
            #pragma unroll 4
            for (int jj = 0; jj < 32; jj++) {
                int j = j0 + jj;            // warp-uniform -> broadcast LDS
                if (iou_sup(bi, ai, s_box[j], s_area[j])) m |= (1u << jj);
            }
        } else if (j0 + 31 > i) {
            #pragma unroll 4
            for (int jj = 0; jj < 32; jj++) {
                int j = j0 + jj;
                if (j <= i) continue;
                if (iou_sup(bi, ai, s_box[j], s_area[j])) m |= (1u << jj);
            }
        }
        if (w >= (i >> 5)) supb[(w << 10) + i] = m;   // upper tri only
        if (m) s_rowf[i] = 1;               // benign race (writes of 1)
    }
    __syncthreads();
    for (int r = tid; r < KC; r += NT) {
        unsigned int bal = __ballot_sync(0xffffffffu, s_rowf[r] != 0);
        if (lane == 0)
            g_rowany[((b * SLICES + slice) << 5) + (r >> 5)] = bal;
    }
}

// ===================== kB: vector stage (w-major planes) + scan + output =====
#define KB_SUP    0                       // 32*1028*4 = 131584
#define KB_BOX    131584                  // float4[1024] = 16384
#define KB_SC     147968                  // 4096
#define KB_RAW    152064                  // u32[32]
#define KB_VALW   152192                  // u32[32]
#define KB_KEEPW  152320                  // u32[32]
#define KB_DIAG   152448                  // u32[32]
#define KB_TOTAL  152576

__global__ __launch_bounds__(NT, 1)
void kB_scan(float* __restrict__ out, int out_size)
{
    extern __shared__ unsigned char sm[];
    unsigned int*  s_sup   = (unsigned int*)(sm + KB_SUP);
    float4*        s_box   = (float4*)(sm + KB_BOX);
    float*         s_sc    = (float*)(sm + KB_SC);
    unsigned int*  s_raw   = (unsigned int*)(sm + KB_RAW);
    unsigned int*  s_validw= (unsigned int*)(sm + KB_VALW);
    unsigned int*  s_keepw = (unsigned int*)(sm + KB_KEEPW);
    unsigned int*  s_diagm = (unsigned int*)(sm + KB_DIAG);

    const int b    = blockIdx.x;
    const int tid  = threadIdx.x;
    const int lane = tid & 31;
    const unsigned FULL = 0xffffffffu;

    // ---- stage sup matrix: LDG.128 -> STS.128 into w-major planes ----
    const unsigned int* supb = g_sup + (size_t)b * WORDS * KC;
    const uint4* sup4 = (const uint4*)supb;
    #pragma unroll 4
    for (int t = tid; t < (WORDS * KC) / 4; t += NT) {
        int w  = t >> 8;            // word plane
        int i4 = (t & 255) << 2;    // row group of 4 (same i>>5 for all 4)
        if (w < (i4 >> 5)) continue;   // strict lower tri: never read
        uint4 v = sup4[t];
        *(uint4*)(s_sup + w * PLANE + i4) = v;
    }

    // ---- validity + rowany + boxes ----
    for (int t = tid; t < KC; t += NT) {
        size_t o = (size_t)b * KC + t;
        s_box[t] = g_box[o];
        float sc = __uint_as_float((unsigned int)(g_keys[o] >> 32));
        s_sc[t] = sc;
        unsigned int bal = __ballot_sync(FULL, sc > 0.5f);
        if (lane == 0) s_validw[t >> 5] = bal;
    }
    if (tid < 32) {
        unsigned int ra = 0;
        #pragma unroll
        for (int sl = 0; sl < SLICES; sl++)
            ra |= g_rowany[((b * SLICES + sl) << 5) + tid];
        s_raw[tid] = ra;
    }
    __syncthreads();

    // ---- diag mask: rows with nonzero diagonal word ----
    for (int t = tid; t < KC; t += NT) {
        int w = t >> 5;   // warp-uniform
        bool dg = (s_sup[w * PLANE + t] != 0u);
        unsigned int bal = __ballot_sync(FULL, dg);
        if (lane == 0) s_diagm[w] = bal & s_raw[w] & s_validw[w];
    }
    __syncthreads();

    // ---- greedy scan: one warp, diag serial chain + batched applies ----
    if (tid < 32) {
        unsigned int remv = 0;   // lane holds removed-mask for column word lane
        for (int w = 0; w < 32; w++) {
            unsigned int rm_w = __shfl_sync(FULL, remv, w);
            unsigned int vw = s_validw[w];
            unsigned int ra = s_raw[w];
            unsigned int diag = s_diagm[w];
            unsigned int kw = 0;
            unsigned int remaining = vw & ra;
            for (;;) {
                unsigned int scand = remaining & ~rm_w;
                if (!scand) break;
                unsigned int dcand = scand & diag;
                if (!dcand) { kw |= scand; break; }
                int d = __ffs(dcand) - 1;
                unsigned int below = scand & ((1u << d) - 1u);
                kw |= below | (1u << d);
                remaining &= ~(below | (1u << d));
                rm_w |= s_sup[w * PLANE + (w << 5) + d];  // broadcast LDS
            }
            kw |= vw & ~ra & ~rm_w;
            if (lane == 0) s_keepw[w] = kw;
            // batch apply: kept suppressors -> columns >= w (upper tri)
            unsigned int app = kw & ra;
            while (app) {
                int bit = __ffs(app) - 1;
                app &= app - 1u;
                if (lane >= w)
                    remv |= s_sup[lane * PLANE + (w << 5) + bit];
            }
        }
    }
    __syncthreads();

    // ---- outputs: dets [B,KC,5], keep [B,KC] ----
    const bool write_keep = (out_size >= BB * KC * 6);
    for (int t = tid; t < KC; t += NT) {
        bool kept = (s_keepw[t >> 5] >> (t & 31)) & 1u;
        float kf = kept ? 1.0f : 0.0f;
        float4 bx = s_box[t];
        size_t base = ((size_t)b * KC + t) * 5;
        out[base + 0] = __fmul_rn(bx.x, kf);
        out[base + 1] = __fmul_rn(bx.y, kf);
        out[base + 2] = __fmul_rn(bx.z, kf);
        out[base + 3] = __fmul_rn(bx.w, kf);
        out[base + 4] = __fmul_rn(s_sc[t], kf);
        if (write_keep)
            out[(size_t)BB * KC * 5 + (size_t)b * KC + t] = kf;
    }
}

// ======================= launch ==============================================
extern "C" void kernel_launch(void* const* d_in, const int* in_sizes, int n_in,
                              void* d_out, int out_size)
{
    (void)in_sizes; (void)n_in;
    cudaFuncSetAttribute(kHA,
        cudaFuncAttributeMaxDynamicSharedMemorySize, KA_TOTAL);
    cudaFuncSetAttribute(kB_scan,
        cudaFuncAttributeMaxDynamicSharedMemorySize, KB_TOTAL);
    const float* locs   = (const float*)d_in[0];
    const float* confs  = (const float*)d_in[1];
    const float* priors = (const float*)d_in[2];
    float* out = (float*)d_out;

    kHA<<<dim3(2, BB), NTA, KA_TOTAL>>>(locs, confs, priors);
    kS_supmat<<<dim3(SLICES, BB), NT>>>();
    kB_scan<<<BB, NT, KB_TOTAL>>>(out, out_size);
}